// round 13
// baseline (speedup 1.0000x reference)
#include <cuda_runtime.h>
#include <cuda_bf16.h>
#include <math.h>

#define N_NODES 50000
#define N_EDGES 800000
#define DIM 64

// ---- static scratch ----
__device__ __align__(16) float g_p[N_NODES * DIM];   // h @ w_flat^T
__device__ __align__(16) float g_A[N_NODES * 8];     // per-node unnormalized accumulator
__device__ float g_s[N_NODES];
__device__ float g_d[N_NODES];
__device__ float g_denom[N_NODES];

union F4U { float4 f; unsigned long long u[2]; };

__device__ __forceinline__ unsigned long long f32x2_dup(float x) {
    unsigned long long r;
    unsigned int xi = __float_as_uint(x);
    asm("mov.b64 %0, {%1, %1};" : "=l"(r) : "r"(xi));
    return r;
}
__device__ __forceinline__ unsigned long long fma_f32x2(
    unsigned long long a, unsigned long long b, unsigned long long c) {
    unsigned long long d;
    asm("fma.rn.f32x2 %0, %1, %2, %3;" : "=l"(d) : "l"(a), "l"(b), "l"(c));
    return d;
}

// ============================================================================
// k_node: 64-node x 64-out tile, 64 threads, 8x8 FFMA2 microtile (R12-proven
// mainloop). 32.5KB smem -> ~7 blocks/SM residency vs grid 782 (5.3/SM) =>
// single wave, no tail quantization.
// ============================================================================
__global__ void __launch_bounds__(64) k_node(
    const float* __restrict__ h, const float* __restrict__ w,
    const float* __restrict__ attn) {
    __shared__ float sHt[DIM * 64];    // sHt[i*64 + r] = h[n0+r][i]      (16KB)
    __shared__ float sWtS[8 * 516];    // sWtS[oq*516 + i*8 + k] = w[(8oq+k)*64+i]

    int tid = threadIdx.x;             // 0..63
    int n0 = blockIdx.x * 64;
    int nrem = N_NODES - n0;           // last block: 16

    // --- W fill: thread o transposes w row o into the slab (8 LDG.128, 32 STS) ---
    {
        int o = tid;
        int oq = o >> 3, k = o & 7;
        const float4* wrow = reinterpret_cast<const float4*>(w + o * DIM);
        float* slab = &sWtS[oq * 516 + k];
#pragma unroll
        for (int j = 0; j < 16; j++) {
            float4 v = __ldg(wrow + j);
            int i0 = j * 4;
            slab[(i0 + 0) * 8] = v.x;
            slab[(i0 + 1) * 8] = v.y;
            slab[(i0 + 2) * 8] = v.z;
            slab[(i0 + 3) * 8] = v.w;
        }
    }
    // --- H fill: thread r transposes h row n0+r (16 LDG.128, 64 STS) ---
    {
        int r = tid;
        bool valid = (r < nrem);
        const float4* hrow = reinterpret_cast<const float4*>(
            h + (size_t)(n0 + (valid ? r : 0)) * DIM);
        float4 z = make_float4(0.f, 0.f, 0.f, 0.f);
#pragma unroll
        for (int c4 = 0; c4 < 16; c4++) {
            float4 v = valid ? __ldg(hrow + c4) : z;
            int c = c4 * 4;
            sHt[(c + 0) * 64 + r] = v.x;
            sHt[(c + 1) * 64 + r] = v.y;
            sHt[(c + 2) * 64 + r] = v.z;
            sHt[(c + 3) * 64 + r] = v.w;
        }
    }
    __syncthreads();

    // --- 8x8 microtile: nodes 8*nq (nq 0..7), outputs 8*oq (oq 0..7) ---
    int nq = tid >> 3;
    int oq = tid & 7;
    unsigned long long acc[8][4];
#pragma unroll
    for (int a = 0; a < 8; a++)
#pragma unroll
        for (int bp = 0; bp < 4; bp++) acc[a][bp] = 0ull;

    const float* wslab = &sWtS[oq * 516];

#pragma unroll 4
    for (int i = 0; i < DIM; i++) {
        const float4* hp = reinterpret_cast<const float4*>(&sHt[i * 64 + 8 * nq]);
        float4 h0 = hp[0], h1 = hp[1];
        F4U w0, w1;
        w0.f = *reinterpret_cast<const float4*>(wslab + i * 8);
        w1.f = *reinterpret_cast<const float4*>(wslab + i * 8 + 4);
        unsigned long long wp[4] = {w0.u[0], w0.u[1], w1.u[0], w1.u[1]};
        float hv[8] = {h0.x, h0.y, h0.z, h0.w, h1.x, h1.y, h1.z, h1.w};
#pragma unroll
        for (int a = 0; a < 8; a++) {
            unsigned long long ha = f32x2_dup(hv[a]);
#pragma unroll
            for (int bp = 0; bp < 4; bp++)
                acc[a][bp] = fma_f32x2(ha, wp[bp], acc[a][bp]);
        }
    }
#pragma unroll
    for (int a = 0; a < 8; a++) {
        int rl = 8 * nq + a;
        if (rl < nrem) {
            F4U o0, o1;
            o0.u[0] = acc[a][0]; o0.u[1] = acc[a][1];
            o1.u[0] = acc[a][2]; o1.u[1] = acc[a][3];
            float* dst = &g_p[(size_t)(n0 + rl) * DIM + 8 * oq];
            *reinterpret_cast<float4*>(dst) = o0.f;
            *reinterpret_cast<float4*>(dst + 4) = o1.f;
        }
    }

    // --- per-node attention scalars + zero init (one node per thread) ---
    if (tid < nrem) {
        float s = 0.f, d = 0.f;
#pragma unroll 8
        for (int i = 0; i < DIM; i++) {
            float hv = sHt[i * 64 + tid];
            s = fmaf(hv, __ldg(attn + i), s);
            d = fmaf(hv, __ldg(attn + 64 + i), d);
        }
        int n = n0 + tid;
        g_s[n] = s;
        g_d[n] = d;
        g_denom[n] = 0.0f;
        float4 z = make_float4(0.f, 0.f, 0.f, 0.f);
        *reinterpret_cast<float4*>(&g_A[n * 8]) = z;
        *reinterpret_cast<float4*>(&g_A[n * 8 + 4]) = z;
    }
}

// ============================================================================
// Fused edge pass, 4 edges/thread (int4 index loads, 4 independent gather
// chains for MLP): denom[dn] += ex ; A[dn] += ex * p[sn, 8r..8r+7].
// ============================================================================
__global__ void k_edge(const int* __restrict__ src, const int* __restrict__ dst,
                       const int* __restrict__ we) {
    int t = blockIdx.x * blockDim.x + threadIdx.x;
    if (t >= N_EDGES / 4) return;
    int4 s4 = __ldg(reinterpret_cast<const int4*>(src) + t);
    int4 d4 = __ldg(reinterpret_cast<const int4*>(dst) + t);
    int4 r4 = __ldg(reinterpret_cast<const int4*>(we) + t);
    int sn[4] = {s4.x, s4.y, s4.z, s4.w};
    int dn[4] = {d4.x, d4.y, d4.z, d4.w};
    int rr[4] = {r4.x, r4.y, r4.z, r4.w};

    float sv[4], dv[4];
    float4 p0[4], p1[4];
#pragma unroll
    for (int j = 0; j < 4; j++) {
        sv[j] = __ldg(&g_s[sn[j]]);
        dv[j] = __ldg(&g_d[dn[j]]);
        const float4* pr = reinterpret_cast<const float4*>(
            g_p + (size_t)sn[j] * DIM + rr[j] * 8);
        p0[j] = __ldg(pr);
        p1[j] = __ldg(pr + 1);
    }
#pragma unroll
    for (int j = 0; j < 4; j++) {
        float x = sv[j] + dv[j];
        float v = (x > 0.0f) ? x : 0.01f * x;
        float ex = __expf(v);
        atomicAdd(&g_denom[dn[j]], ex);
        float4* arow = reinterpret_cast<float4*>(g_A + dn[j] * 8);
        atomicAdd(&arow[0],
                  make_float4(ex * p0[j].x, ex * p0[j].y, ex * p0[j].z, ex * p0[j].w));
        atomicAdd(&arow[1],
                  make_float4(ex * p1[j].x, ex * p1[j].y, ex * p1[j].z, ex * p1[j].w));
    }
}

// ============================================================================
// Expand (proven): out[n, o] = w_comp[o & 7] * A[n, o >> 3] / max(denom, 1e-38).
// ============================================================================
#define HALF_F4 (N_NODES * 8)
__global__ void k_expand(const float* __restrict__ w_comp, float* __restrict__ out) {
    int t = blockIdx.x * blockDim.x + threadIdx.x;
    if (t >= HALF_F4) return;
    float4 wc0 = __ldg(reinterpret_cast<const float4*>(w_comp));
    float4 wc1 = __ldg(reinterpret_cast<const float4*>(w_comp) + 1);
#pragma unroll
    for (int half = 0; half < 2; half++) {
        int t4 = t + half * HALF_F4;
        int n = t4 >> 4;
        int k = t4 & 15;
        float inv = __fdividef(1.0f, fmaxf(g_denom[n], 1e-38f));
        float a = g_A[n * 8 + (k >> 1)] * inv;
        float4 wc = (k & 1) ? wc1 : wc0;
        reinterpret_cast<float4*>(out)[t4] =
            make_float4(a * wc.x, a * wc.y, a * wc.z, a * wc.w);
    }
}

extern "C" void kernel_launch(void* const* d_in, const int* in_sizes, int n_in,
                              void* d_out, int out_size) {
    const float* h      = (const float*)d_in[0];
    const int*   src    = (const int*)d_in[1];
    const int*   dst    = (const int*)d_in[2];
    const int*   we     = (const int*)d_in[3];
    const float* w      = (const float*)d_in[4];
    const float* w_comp = (const float*)d_in[5];
    const float* attn   = (const float*)d_in[6];
    float* out = (float*)d_out;
    (void)in_sizes; (void)n_in; (void)out_size;

    k_node<<<(N_NODES + 63) / 64, 64>>>(h, w, attn);
    k_edge<<<(N_EDGES / 4 + 255) / 256, 256>>>(src, dst, we);
    k_expand<<<(HALF_F4 + 255) / 256, 256>>>(w_comp, out);
}